// round 12
// baseline (speedup 1.0000x reference)
#include <cuda_runtime.h>
#include <cstdint>

#define NN 50000
#define EE 800000
#define FF 64
#define HH 64
#define H2 128
#define CC 40
#define LL 3
#define BN_EPS 1e-5f
#define MAXDEG 128

__device__ __align__(16) float g_x[NN * FF];
__device__ __align__(16) float g_agg[NN * FF];
__device__ int g_is32;

// direct-slot CSR
__device__ int g_deg[NN];
__device__ int g_colidx[NN * MAXDEG];

// ---------------------------------------------------------------------------
// f32x2 helpers (sm_103a packed dual-fp32)
// ---------------------------------------------------------------------------
__device__ __forceinline__ unsigned long long ffma2(
    unsigned long long a, unsigned long long b, unsigned long long c) {
    unsigned long long d;
    asm("fma.rn.f32x2 %0, %1, %2, %3;" : "=l"(d) : "l"(a), "l"(b), "l"(c));
    return d;
}
__device__ __forceinline__ unsigned long long pack2(float v) {
    unsigned long long d;
    unsigned int u = __float_as_uint(v);
    asm("mov.b64 %0, {%1, %2};" : "=l"(d) : "r"(u), "r"(u));
    return d;
}
__device__ __forceinline__ void unpack2(unsigned long long d, float& lo, float& hi) {
    unsigned int a, b;
    asm("mov.b64 {%0, %1}, %2;" : "=r"(a), "=r"(b) : "l"(d));
    lo = __uint_as_float(a);
    hi = __uint_as_float(b);
}

// ---------------------------------------------------------------------------
__global__ void detect_kernel(const long long* __restrict__ ei) {
    long long v = ei[threadIdx.x];
    int bad = (v < 0 || v >= NN) ? 1 : 0;
    int any = __syncthreads_or(bad);
    if (threadIdx.x == 0) g_is32 = any;
}

__global__ void fill_kernel(const void* __restrict__ ei) {
    int e = blockIdx.x * blockDim.x + threadIdx.x;
    if (e >= EE) return;
    int src, dst;
    if (g_is32) {
        src = __ldg((const int*)ei + e);
        dst = __ldg((const int*)ei + EE + e);
    } else {
        src = (int)__ldg((const long long*)ei + e);
        dst = (int)__ldg((const long long*)ei + EE + e);
    }
    if ((unsigned)src >= NN || (unsigned)dst >= NN) return;
    int pos = atomicAdd(&g_deg[dst], 1);
    if (pos < MAXDEG) g_colidx[dst * MAXDEG + pos] = src;
}

// ---------------------------------------------------------------------------
// CSR gather: agg[i] = x[i] + sum_{j in N(i)} x[j].  (unchanged)
// ---------------------------------------------------------------------------
__global__ __launch_bounds__(256) void gather_kernel(
    const float* __restrict__ x, float* __restrict__ agg)
{
    const int warp = (blockIdx.x * blockDim.x + threadIdx.x) >> 5;
    if (warp >= NN) return;
    const int lane = threadIdx.x & 31;
    const int half = lane >> 4;
    const int sub  = lane & 15;

    const int start = warp * MAXDEG;
    const int end   = start + min(g_deg[warp], MAXDEG);

    float4 acc = make_float4(0.f, 0.f, 0.f, 0.f);
    if (half == 0)
        acc = *(const float4*)(x + (size_t)warp * 64 + sub * 4);

    int k = start + half;
    for (; k + 6 < end; k += 8) {
        const int i0 = __ldg(g_colidx + k);
        const int i1 = __ldg(g_colidx + k + 2);
        const int i2 = __ldg(g_colidx + k + 4);
        const int i3 = __ldg(g_colidx + k + 6);
        const float4 v0 = *(const float4*)(x + (size_t)i0 * 64 + sub * 4);
        const float4 v1 = *(const float4*)(x + (size_t)i1 * 64 + sub * 4);
        const float4 v2 = *(const float4*)(x + (size_t)i2 * 64 + sub * 4);
        const float4 v3 = *(const float4*)(x + (size_t)i3 * 64 + sub * 4);
        acc.x += v0.x + v1.x + v2.x + v3.x;
        acc.y += v0.y + v1.y + v2.y + v3.y;
        acc.z += v0.z + v1.z + v2.z + v3.z;
        acc.w += v0.w + v1.w + v2.w + v3.w;
    }
    for (; k < end; k += 2) {
        const int i = __ldg(g_colidx + k);
        const float4 v = *(const float4*)(x + (size_t)i * 64 + sub * 4);
        acc.x += v.x; acc.y += v.y; acc.z += v.z; acc.w += v.w;
    }

    acc.x += __shfl_xor_sync(0xffffffffu, acc.x, 16);
    acc.y += __shfl_xor_sync(0xffffffffu, acc.y, 16);
    acc.z += __shfl_xor_sync(0xffffffffu, acc.z, 16);
    acc.w += __shfl_xor_sync(0xffffffffu, acc.w, 16);

    if (half == 0)
        *(float4*)(agg + (size_t)warp * 64 + sub * 4) = acc;
}

// ---------------------------------------------------------------------------
// FFMA2 MLP, 1024 threads (32 warps) per block, 128-node tile.
// Activations pre-duplicated into f32x2 pairs in smem (xs2) at tile load ->
// zero packs in the GEMM1 hot loop.
// smem (floats): W1 8192 + W2 8192 + a1/c1/a2/c2 384 + xs2 16384 + hs 16384
//   = 49,536 floats = 198,144 B  (1 block/SM, 32 warps)
// Layout offsets: W1s 0, W2s 8192, a1 16384, c1 16512, a2 16640, c2 16704,
//   xs2 @ 16768 (16B aligned), hs @ 33152.
// ---------------------------------------------------------------------------
#define MLP_SHM_FLOATS 49536
#define MLP_SHM_BYTES  (MLP_SHM_FLOATS * 4)

__global__ __launch_bounds__(1024) void mlp_kernel(
    const float* __restrict__ hin,
    const float* __restrict__ W1, const float* __restrict__ b1,
    const float* __restrict__ g1, const float* __restrict__ bt1,
    const float* __restrict__ m1, const float* __restrict__ v1,
    const float* __restrict__ W2, const float* __restrict__ b2,
    const float* __restrict__ gc, const float* __restrict__ bc,
    const float* __restrict__ mc, const float* __restrict__ vc,
    float* __restrict__ xout)
{
    extern __shared__ float sm[];
    float* W1s = sm;                        // [64][128]
    float* W2s = W1s + 8192;                // [128][64]
    float* a1  = W2s + 8192;                // [128]
    float* c1  = a1 + 128;                  // [128]
    float* a2  = c1 + 128;                  // [64]
    float* c2  = a2 + 64;                   // [64]
    unsigned long long* xs2 =
        (unsigned long long*)(sm + 16768);  // [128][64] f32x2 pairs
    float* hs  = sm + 33152;                // [128][128]

    const int tid  = threadIdx.x;
    const int warp = tid >> 5;
    const int lane = tid & 31;

    for (int i = tid; i < 8192; i += 1024) W1s[i] = W1[i];
    for (int i = tid; i < 8192; i += 1024) W2s[i] = W2[i];
    if (tid < 128) {
        float a = g1[tid] * rsqrtf(v1[tid] + BN_EPS);
        a1[tid] = a;
        c1[tid] = (b1[tid] - m1[tid]) * a + bt1[tid];
    } else if (tid < 192) {
        int j = tid - 128;
        float a = gc[j] * rsqrtf(vc[j] + BN_EPS);
        a2[j] = a;
        c2[j] = (b2[j] - mc[j]) * a + bc[j];
    }
    __syncthreads();

    const int ntiles = (NN + 127) >> 7;
    for (int tile = blockIdx.x; tile < ntiles; tile += gridDim.x) {
        const int base = tile << 7;

        // tile load -> duplicated f32x2 pairs
        for (int i = tid; i < 2048; i += 1024) {
            int node = i >> 4;
            float4 v;
            if (base + node < NN)
                v = *(const float4*)(hin + (size_t)(base + node) * 64 + (i & 15) * 4);
            else
                v = make_float4(0.f, 0.f, 0.f, 0.f);
            unsigned long long* dst = xs2 + node * 64 + (i & 15) * 4;
            dst[0] = pack2(v.x);
            dst[1] = pack2(v.y);
            dst[2] = pack2(v.z);
            dst[3] = pack2(v.w);
        }
        __syncthreads();

        // ---- GEMM1: warp owns 4 nodes; lane covers j0=lane*4 ----
        {
            const int j0 = lane * 4;
            const int nb = warp * 4;
            unsigned long long acc01[4], acc23[4];
            #pragma unroll
            for (int n = 0; n < 4; n++) { acc01[n] = 0ULL; acc23[n] = 0ULL; }

            for (int k4 = 0; k4 < 16; k4++) {
                ulonglong2 wk0 = *(const ulonglong2*)(W1s + (k4 * 4 + 0) * 128 + j0);
                ulonglong2 wk1 = *(const ulonglong2*)(W1s + (k4 * 4 + 1) * 128 + j0);
                ulonglong2 wk2 = *(const ulonglong2*)(W1s + (k4 * 4 + 2) * 128 + j0);
                ulonglong2 wk3 = *(const ulonglong2*)(W1s + (k4 * 4 + 3) * 128 + j0);
                #pragma unroll
                for (int n = 0; n < 4; n++) {
                    const ulonglong2 xa = *(const ulonglong2*)(xs2 + (nb + n) * 64 + k4 * 4);
                    const ulonglong2 xb = *(const ulonglong2*)(xs2 + (nb + n) * 64 + k4 * 4 + 2);
                    acc01[n] = ffma2(xa.x, wk0.x, acc01[n]);
                    acc23[n] = ffma2(xa.x, wk0.y, acc23[n]);
                    acc01[n] = ffma2(xa.y, wk1.x, acc01[n]);
                    acc23[n] = ffma2(xa.y, wk1.y, acc23[n]);
                    acc01[n] = ffma2(xb.x, wk2.x, acc01[n]);
                    acc23[n] = ffma2(xb.x, wk2.y, acc23[n]);
                    acc01[n] = ffma2(xb.y, wk3.x, acc01[n]);
                    acc23[n] = ffma2(xb.y, wk3.y, acc23[n]);
                }
            }
            const float4 A = *(const float4*)(a1 + j0);
            const float4 C = *(const float4*)(c1 + j0);
            #pragma unroll
            for (int n = 0; n < 4; n++) {
                float f0, f1, f2, f3;
                unpack2(acc01[n], f0, f1);
                unpack2(acc23[n], f2, f3);
                float4 h;
                h.x = fmaxf(fmaf(f0, A.x, C.x), 0.f);
                h.y = fmaxf(fmaf(f1, A.y, C.y), 0.f);
                h.z = fmaxf(fmaf(f2, A.z, C.z), 0.f);
                h.w = fmaxf(fmaf(f3, A.w, C.w), 0.f);
                *(float4*)(hs + (nb + n) * 128 + j0) = h;
            }
        }
        __syncthreads();

        // ---- GEMM2: warp owns 4 nodes; lane: j0=(lane&15)*4, half picks 2 nodes ----
        {
            const int j0 = (lane & 15) * 4;
            const int nb = warp * 4 + (lane >> 4) * 2;
            unsigned long long acc01[2], acc23[2];
            #pragma unroll
            for (int n = 0; n < 2; n++) { acc01[n] = 0ULL; acc23[n] = 0ULL; }

            for (int k4 = 0; k4 < 32; k4++) {
                ulonglong2 wk0 = *(const ulonglong2*)(W2s + (k4 * 4 + 0) * 64 + j0);
                ulonglong2 wk1 = *(const ulonglong2*)(W2s + (k4 * 4 + 1) * 64 + j0);
                ulonglong2 wk2 = *(const ulonglong2*)(W2s + (k4 * 4 + 2) * 64 + j0);
                ulonglong2 wk3 = *(const ulonglong2*)(W2s + (k4 * 4 + 3) * 64 + j0);
                #pragma unroll
                for (int n = 0; n < 2; n++) {
                    const float4 hv = *(const float4*)(hs + (nb + n) * 128 + k4 * 4);
                    unsigned long long xp;
                    xp = pack2(hv.x);
                    acc01[n] = ffma2(xp, wk0.x, acc01[n]);
                    acc23[n] = ffma2(xp, wk0.y, acc23[n]);
                    xp = pack2(hv.y);
                    acc01[n] = ffma2(xp, wk1.x, acc01[n]);
                    acc23[n] = ffma2(xp, wk1.y, acc23[n]);
                    xp = pack2(hv.z);
                    acc01[n] = ffma2(xp, wk2.x, acc01[n]);
                    acc23[n] = ffma2(xp, wk2.y, acc23[n]);
                    xp = pack2(hv.w);
                    acc01[n] = ffma2(xp, wk3.x, acc01[n]);
                    acc23[n] = ffma2(xp, wk3.y, acc23[n]);
                }
            }
            const float4 A = *(const float4*)(a2 + j0);
            const float4 C = *(const float4*)(c2 + j0);
            #pragma unroll
            for (int n = 0; n < 2; n++) {
                const int node = base + nb + n;
                if (node < NN) {
                    float f0, f1, f2, f3;
                    unpack2(acc01[n], f0, f1);
                    unpack2(acc23[n], f2, f3);
                    float4 o;
                    o.x = fmaxf(fmaf(f0, A.x, C.x), 0.f);
                    o.y = fmaxf(fmaf(f1, A.y, C.y), 0.f);
                    o.z = fmaxf(fmaf(f2, A.z, C.z), 0.f);
                    o.w = fmaxf(fmaf(f3, A.w, C.w), 0.f);
                    *(float4*)(xout + (size_t)node * 64 + j0) = o;
                }
            }
        }
        __syncthreads();
    }
}

// ---------------------------------------------------------------------------
// Register-tiled head (unchanged).
// ---------------------------------------------------------------------------
#define HEAD_SHM_FLOATS 32960
#define HEAD_SHM_BYTES  (HEAD_SHM_FLOATS * 4)

__global__ __launch_bounds__(512) void head_kernel(
    const float* __restrict__ x,
    const float* __restrict__ lin1_W, const float* __restrict__ lin1_b,
    const float* __restrict__ g,  const float* __restrict__ b,
    const float* __restrict__ m,  const float* __restrict__ v,
    const float* __restrict__ lin2_W, const float* __restrict__ lin2_b,
    float* __restrict__ out)
{
    extern __shared__ float sm[];
    float* W1s = sm;             // [64][64]
    float* W2s = W1s + 4096;     // [64][64] (cols 40..63 zero)
    float* a1  = W2s + 4096;     // [64]
    float* c1  = a1 + 64;        // [64]
    float* c2  = c1 + 64;        // [64]
    float* xs  = c2 + 64;        // [128][64]
    float* ts  = xs + 8192;      // [128][64]
    float* ls  = ts + 8192;      // [128][64]

    const int tid  = threadIdx.x;
    const int warp = tid >> 5;
    const int lane = tid & 31;

    for (int i = tid; i < 4096; i += 512) W1s[i] = lin1_W[i];
    for (int i = tid; i < 4096; i += 512) {
        int col = i & 63;
        W2s[i] = (col < CC) ? lin2_W[(i >> 6) * CC + col] : 0.0f;
    }
    if (tid < 64) {
        float a = g[tid] * rsqrtf(v[tid] + BN_EPS);
        a1[tid] = a;
        c1[tid] = (lin1_b[tid] - m[tid]) * a + b[tid];
    } else if (tid < 128) {
        int j = tid - 64;
        c2[j] = (j < CC) ? lin2_b[j] : 0.0f;
    }
    __syncthreads();

    const int ntiles = (NN + 127) >> 7;
    for (int tile = blockIdx.x; tile < ntiles; tile += gridDim.x) {
        const int base = tile << 7;

        for (int i = tid; i < 2048; i += 512) {
            int node = i >> 4;
            float4 vv;
            if (base + node < NN)
                vv = *(const float4*)(x + (size_t)(base + node) * 64 + (i & 15) * 4);
            else
                vv = make_float4(0.f, 0.f, 0.f, 0.f);
            *(float4*)(xs + i * 4) = vv;
        }
        __syncthreads();

        {
            const int j0 = lane * 2;
            float2 acc[8];
            #pragma unroll
            for (int n = 0; n < 8; n++) acc[n] = make_float2(0.f, 0.f);
            const float* xrow = xs + (warp * 8) * 64;

            for (int k4 = 0; k4 < 16; k4++) {
                const float2 w0 = *(const float2*)(W1s + (k4 * 4 + 0) * 64 + j0);
                const float2 w1 = *(const float2*)(W1s + (k4 * 4 + 1) * 64 + j0);
                const float2 w2 = *(const float2*)(W1s + (k4 * 4 + 2) * 64 + j0);
                const float2 w3 = *(const float2*)(W1s + (k4 * 4 + 3) * 64 + j0);
                #pragma unroll
                for (int n = 0; n < 8; n++) {
                    const float4 xv = *(const float4*)(xrow + n * 64 + k4 * 4);
                    acc[n].x = fmaf(xv.x, w0.x, acc[n].x);
                    acc[n].y = fmaf(xv.x, w0.y, acc[n].y);
                    acc[n].x = fmaf(xv.y, w1.x, acc[n].x);
                    acc[n].y = fmaf(xv.y, w1.y, acc[n].y);
                    acc[n].x = fmaf(xv.z, w2.x, acc[n].x);
                    acc[n].y = fmaf(xv.z, w2.y, acc[n].y);
                    acc[n].x = fmaf(xv.w, w3.x, acc[n].x);
                    acc[n].y = fmaf(xv.w, w3.y, acc[n].y);
                }
            }
            const float A0 = a1[j0], A1 = a1[j0 + 1];
            const float C0 = c1[j0], C1 = c1[j0 + 1];
            #pragma unroll
            for (int n = 0; n < 8; n++) {
                float2 t;
                t.x = fmaxf(fmaf(acc[n].x, A0, C0), 0.f);
                t.y = fmaxf(fmaf(acc[n].y, A1, C1), 0.f);
                *(float2*)(ts + (warp * 8 + n) * 64 + j0) = t;
            }
        }
        __syncthreads();

        {
            const int j0 = lane * 2;
            float2 acc[8];
            #pragma unroll
            for (int n = 0; n < 8; n++) acc[n] = make_float2(0.f, 0.f);
            const float* trow = ts + (warp * 8) * 64;

            for (int k4 = 0; k4 < 16; k4++) {
                const float2 w0 = *(const float2*)(W2s + (k4 * 4 + 0) * 64 + j0);
                const float2 w1 = *(const float2*)(W2s + (k4 * 4 + 1) * 64 + j0);
                const float2 w2 = *(const float2*)(W2s + (k4 * 4 + 2) * 64 + j0);
                const float2 w3 = *(const float2*)(W2s + (k4 * 4 + 3) * 64 + j0);
                #pragma unroll
                for (int n = 0; n < 8; n++) {
                    const float4 tv = *(const float4*)(trow + n * 64 + k4 * 4);
                    acc[n].x = fmaf(tv.x, w0.x, acc[n].x);
                    acc[n].y = fmaf(tv.x, w0.y, acc[n].y);
                    acc[n].x = fmaf(tv.y, w1.x, acc[n].x);
                    acc[n].y = fmaf(tv.y, w1.y, acc[n].y);
                    acc[n].x = fmaf(tv.z, w2.x, acc[n].x);
                    acc[n].y = fmaf(tv.z, w2.y, acc[n].y);
                    acc[n].x = fmaf(tv.w, w3.x, acc[n].x);
                    acc[n].y = fmaf(tv.w, w3.y, acc[n].y);
                }
            }
            const float C0 = c2[j0], C1 = c2[j0 + 1];
            #pragma unroll
            for (int n = 0; n < 8; n++) {
                float2 o;
                o.x = acc[n].x + C0;
                o.y = acc[n].y + C1;
                *(float2*)(ls + (warp * 8 + n) * 64 + j0) = o;
            }
        }
        __syncthreads();

        for (int n = 0; n < 8; n++) {
            const int node = base + warp * 8 + n;
            if (node >= NN) break;
            const float* lr = ls + (warp * 8 + n) * 64;
            float v0 = lr[lane];
            float v1 = (lane < CC - 32) ? lr[32 + lane] : -3.0e38f;
            float mx = fmaxf(v0, v1);
            #pragma unroll
            for (int o = 16; o > 0; o >>= 1)
                mx = fmaxf(mx, __shfl_xor_sync(0xffffffffu, mx, o));
            float s = expf(v0 - mx) + ((lane < CC - 32) ? expf(v1 - mx) : 0.f);
            #pragma unroll
            for (int o = 16; o > 0; o >>= 1)
                s += __shfl_xor_sync(0xffffffffu, s, o);
            const float lse = mx + logf(s);
            float* orow = out + (size_t)node * CC;
            orow[lane] = v0 - lse;
            if (lane < CC - 32) orow[32 + lane] = v1 - lse;
        }
        __syncthreads();
    }
}

// ---------------------------------------------------------------------------
extern "C" void kernel_launch(void* const* d_in, const int* in_sizes, int n_in,
                              void* d_out, int out_size) {
    const float* x = nullptr;
    const void*  ei = nullptr;
    const float* w24[2] = {nullptr, nullptr}; int n24 = 0;
    const float* p384[5] = {0};               int n384 = 0;
    const float* p192[5] = {0};               int n192 = 0;
    const float* p64[5]  = {0};               int n64 = 0;
    const float* lin1_W = nullptr;
    const float* lin2_W = nullptr;
    const float* lin2_b = nullptr;

    for (int i = 0; i < n_in; i++) {
        int s = in_sizes[i];
        const float* p = (const float*)d_in[i];
        if      (s == NN * FF)     x = p;
        else if (s == 2 * EE)      ei = d_in[i];
        else if (s == LL * FF * H2) { if (n24 < 2) w24[n24++] = p; }
        else if (s == LL * H2)     { if (n384 < 5) p384[n384++] = p; }
        else if (s == LL * HH)     { if (n192 < 5) p192[n192++] = p; }
        else if (s == HH * HH)     lin1_W = p;
        else if (s == HH)          { if (n64 < 5) p64[n64++] = p; }
        else if (s == HH * CC)     lin2_W = p;
        else if (s == CC)          lin2_b = p;
    }

    const float* W1s  = w24[0];
    const float* W2s  = w24[1];
    const float* b1s  = p384[0], *g1s = p384[1], *bt1s = p384[2],
               * m1s  = p384[3], *v1s = p384[4];
    const float* b2s  = p192[0], *gcs = p192[1], *bcs = p192[2],
               * mcs  = p192[3], *vcs = p192[4];
    const float* lin1_b = p64[0], *g_bn1 = p64[1], *b_bn1 = p64[2],
               * m_bn1  = p64[3], *v_bn1 = p64[4];

    if (!x || !ei || !W1s || !W2s || !lin1_W || !lin2_W || !lin2_b) return;

    float* gx;   cudaGetSymbolAddress((void**)&gx,   g_x);
    float* gagg; cudaGetSymbolAddress((void**)&gagg, g_agg);
    int*   gdeg; cudaGetSymbolAddress((void**)&gdeg, g_deg);

    cudaFuncSetAttribute(mlp_kernel,  cudaFuncAttributeMaxDynamicSharedMemorySize, MLP_SHM_BYTES);
    cudaFuncSetAttribute(head_kernel, cudaFuncAttributeMaxDynamicSharedMemorySize, HEAD_SHM_BYTES);

    detect_kernel<<<1, 256>>>((const long long*)ei);
    cudaMemsetAsync(gdeg, 0, NN * sizeof(int));
    fill_kernel<<<(EE + 255) / 256, 256>>>(ei);

    const int gather_blocks = (NN * 32 + 255) / 256;

    const float* cur = x;
    for (int l = 0; l < LL; l++) {
        gather_kernel<<<gather_blocks, 256>>>(cur, gagg);
        mlp_kernel<<<148, 1024, MLP_SHM_BYTES>>>(
            gagg,
            W1s + (size_t)l * FF * H2,  b1s + (size_t)l * H2,
            g1s + (size_t)l * H2,       bt1s + (size_t)l * H2,
            m1s + (size_t)l * H2,       v1s + (size_t)l * H2,
            W2s + (size_t)l * H2 * HH,  b2s + (size_t)l * HH,
            gcs + (size_t)l * HH,       bcs + (size_t)l * HH,
            mcs + (size_t)l * HH,       vcs + (size_t)l * HH,
            gx);
        cur = gx;
    }

    head_kernel<<<148, 512, HEAD_SHM_BYTES>>>(
        gx, lin1_W, lin1_b, g_bn1, b_bn1, m_bn1, v_bn1, lin2_W, lin2_b,
        (float*)d_out);
}

// round 13
// speedup vs baseline: 1.0014x; 1.0014x over previous
#include <cuda_runtime.h>
#include <cstdint>

#define NN 50000
#define EE 800000
#define FF 64
#define HH 64
#define H2 128
#define CC 40
#define LL 3
#define BN_EPS 1e-5f
#define MAXDEG 128

__device__ __align__(16) float g_x[NN * FF];
__device__ __align__(16) float g_agg[NN * FF];
__device__ int g_is32;

// direct-slot CSR
__device__ int g_deg[NN];
__device__ int g_colidx[NN * MAXDEG];

// ---------------------------------------------------------------------------
// f32x2 helpers (sm_103a packed dual-fp32)
// ---------------------------------------------------------------------------
__device__ __forceinline__ unsigned long long ffma2(
    unsigned long long a, unsigned long long b, unsigned long long c) {
    unsigned long long d;
    asm("fma.rn.f32x2 %0, %1, %2, %3;" : "=l"(d) : "l"(a), "l"(b), "l"(c));
    return d;
}
__device__ __forceinline__ unsigned long long pack2(float v) {
    unsigned long long d;
    unsigned int u = __float_as_uint(v);
    asm("mov.b64 %0, {%1, %2};" : "=l"(d) : "r"(u), "r"(u));
    return d;
}
__device__ __forceinline__ void unpack2(unsigned long long d, float& lo, float& hi) {
    unsigned int a, b;
    asm("mov.b64 {%0, %1}, %2;" : "=r"(a), "=r"(b) : "l"(d));
    lo = __uint_as_float(a);
    hi = __uint_as_float(b);
}

// ---------------------------------------------------------------------------
__global__ void detect_kernel(const long long* __restrict__ ei) {
    long long v = ei[threadIdx.x];
    int bad = (v < 0 || v >= NN) ? 1 : 0;
    int any = __syncthreads_or(bad);
    if (threadIdx.x == 0) g_is32 = any;
}

__global__ void fill_kernel(const void* __restrict__ ei) {
    int e = blockIdx.x * blockDim.x + threadIdx.x;
    if (e >= EE) return;
    int src, dst;
    if (g_is32) {
        src = __ldg((const int*)ei + e);
        dst = __ldg((const int*)ei + EE + e);
    } else {
        src = (int)__ldg((const long long*)ei + e);
        dst = (int)__ldg((const long long*)ei + EE + e);
    }
    if ((unsigned)src >= NN || (unsigned)dst >= NN) return;
    int pos = atomicAdd(&g_deg[dst], 1);
    if (pos < MAXDEG) g_colidx[dst * MAXDEG + pos] = src;
}

// ---------------------------------------------------------------------------
// CSR gather (unchanged, ~25us/layer).
// ---------------------------------------------------------------------------
__global__ __launch_bounds__(256) void gather_kernel(
    const float* __restrict__ x, float* __restrict__ agg)
{
    const int warp = (blockIdx.x * blockDim.x + threadIdx.x) >> 5;
    if (warp >= NN) return;
    const int lane = threadIdx.x & 31;
    const int half = lane >> 4;
    const int sub  = lane & 15;

    const int start = warp * MAXDEG;
    const int end   = start + min(g_deg[warp], MAXDEG);

    float4 acc = make_float4(0.f, 0.f, 0.f, 0.f);
    if (half == 0)
        acc = *(const float4*)(x + (size_t)warp * 64 + sub * 4);

    int k = start + half;
    for (; k + 6 < end; k += 8) {
        const int i0 = __ldg(g_colidx + k);
        const int i1 = __ldg(g_colidx + k + 2);
        const int i2 = __ldg(g_colidx + k + 4);
        const int i3 = __ldg(g_colidx + k + 6);
        const float4 v0 = *(const float4*)(x + (size_t)i0 * 64 + sub * 4);
        const float4 v1 = *(const float4*)(x + (size_t)i1 * 64 + sub * 4);
        const float4 v2 = *(const float4*)(x + (size_t)i2 * 64 + sub * 4);
        const float4 v3 = *(const float4*)(x + (size_t)i3 * 64 + sub * 4);
        acc.x += v0.x + v1.x + v2.x + v3.x;
        acc.y += v0.y + v1.y + v2.y + v3.y;
        acc.z += v0.z + v1.z + v2.z + v3.z;
        acc.w += v0.w + v1.w + v2.w + v3.w;
    }
    for (; k < end; k += 2) {
        const int i = __ldg(g_colidx + k);
        const float4 v = *(const float4*)(x + (size_t)i * 64 + sub * 4);
        acc.x += v.x; acc.y += v.y; acc.z += v.z; acc.w += v.w;
    }

    acc.x += __shfl_xor_sync(0xffffffffu, acc.x, 16);
    acc.y += __shfl_xor_sync(0xffffffffu, acc.y, 16);
    acc.z += __shfl_xor_sync(0xffffffffu, acc.z, 16);
    acc.w += __shfl_xor_sync(0xffffffffu, acc.w, 16);

    if (half == 0)
        *(float4*)(agg + (size_t)warp * 64 + sub * 4) = acc;
}

// ---------------------------------------------------------------------------
// FFMA2 MLP v3: 64-node tiles, 512 threads, 2 blocks/SM (32 warps/SM).
// Same per-warp LDS pattern as R11 (packs in registers, no duplication);
// BN affine constants live in per-lane registers (each lane only needs its
// own 4 columns), freeing smem so two blocks fit per SM.
// smem: W1 8192 + W2 8192 + xs 4096 + hs 8192 = 28672 floats = 114,688 B.
// ---------------------------------------------------------------------------
#define MLP_SHM_FLOATS 28672
#define MLP_SHM_BYTES  (MLP_SHM_FLOATS * 4)

__global__ __launch_bounds__(512, 2) void mlp_kernel(
    const float* __restrict__ hin,
    const float* __restrict__ W1, const float* __restrict__ b1,
    const float* __restrict__ g1, const float* __restrict__ bt1,
    const float* __restrict__ m1, const float* __restrict__ v1,
    const float* __restrict__ W2, const float* __restrict__ b2,
    const float* __restrict__ gc, const float* __restrict__ bc,
    const float* __restrict__ mc, const float* __restrict__ vc,
    float* __restrict__ xout)
{
    extern __shared__ float sm[];
    float* W1s = sm;             // [64][128]  8192
    float* W2s = W1s + 8192;     // [128][64]  8192
    float* xs  = W2s + 8192;     // [64][64]   4096
    float* hs  = xs + 4096;      // [64][128]  8192

    const int tid  = threadIdx.x;
    const int warp = tid >> 5;
    const int lane = tid & 31;

    for (int i = tid; i < 8192; i += 512) W1s[i] = W1[i];
    for (int i = tid; i < 8192; i += 512) W2s[i] = W2[i];

    // per-lane BN affine constants (registers, loaded once)
    const int j1 = lane * 4;          // GEMM1 columns
    float4 A1v, C1v;
    {
        float a0 = g1[j1+0] * rsqrtf(v1[j1+0] + BN_EPS);
        float a1_ = g1[j1+1] * rsqrtf(v1[j1+1] + BN_EPS);
        float a2_ = g1[j1+2] * rsqrtf(v1[j1+2] + BN_EPS);
        float a3 = g1[j1+3] * rsqrtf(v1[j1+3] + BN_EPS);
        A1v = make_float4(a0, a1_, a2_, a3);
        C1v = make_float4((b1[j1+0]-m1[j1+0])*a0 + bt1[j1+0],
                          (b1[j1+1]-m1[j1+1])*a1_ + bt1[j1+1],
                          (b1[j1+2]-m1[j1+2])*a2_ + bt1[j1+2],
                          (b1[j1+3]-m1[j1+3])*a3 + bt1[j1+3]);
    }
    const int j2 = (lane & 15) * 4;   // GEMM2 columns
    float4 A2v, C2v;
    {
        float a0 = gc[j2+0] * rsqrtf(vc[j2+0] + BN_EPS);
        float a1_ = gc[j2+1] * rsqrtf(vc[j2+1] + BN_EPS);
        float a2_ = gc[j2+2] * rsqrtf(vc[j2+2] + BN_EPS);
        float a3 = gc[j2+3] * rsqrtf(vc[j2+3] + BN_EPS);
        A2v = make_float4(a0, a1_, a2_, a3);
        C2v = make_float4((b2[j2+0]-mc[j2+0])*a0 + bc[j2+0],
                          (b2[j2+1]-mc[j2+1])*a1_ + bc[j2+1],
                          (b2[j2+2]-mc[j2+2])*a2_ + bc[j2+2],
                          (b2[j2+3]-mc[j2+3])*a3 + bc[j2+3]);
    }
    __syncthreads();

    const int ntiles = (NN + 63) >> 6;
    for (int tile = blockIdx.x; tile < ntiles; tile += gridDim.x) {
        const int base = tile << 6;

        // xs load: 64 rows x 16 float4
        for (int i = tid; i < 1024; i += 512) {
            int node = i >> 4;
            float4 v;
            if (base + node < NN)
                v = *(const float4*)(hin + (size_t)(base + node) * 64 + (i & 15) * 4);
            else
                v = make_float4(0.f, 0.f, 0.f, 0.f);
            *(float4*)(xs + i * 4) = v;
        }
        __syncthreads();

        // ---- GEMM1: warp owns 4 nodes; lane covers j1 = lane*4 ----
        {
            const int nb = warp * 4;
            unsigned long long acc01[4], acc23[4];
            #pragma unroll
            for (int n = 0; n < 4; n++) { acc01[n] = 0ULL; acc23[n] = 0ULL; }

            for (int k4 = 0; k4 < 16; k4++) {
                ulonglong2 wk0 = *(const ulonglong2*)(W1s + (k4 * 4 + 0) * 128 + j1);
                ulonglong2 wk1 = *(const ulonglong2*)(W1s + (k4 * 4 + 1) * 128 + j1);
                ulonglong2 wk2 = *(const ulonglong2*)(W1s + (k4 * 4 + 2) * 128 + j1);
                ulonglong2 wk3 = *(const ulonglong2*)(W1s + (k4 * 4 + 3) * 128 + j1);
                #pragma unroll
                for (int n = 0; n < 4; n++) {
                    const float4 xv = *(const float4*)(xs + (nb + n) * 64 + k4 * 4);
                    unsigned long long xp;
                    xp = pack2(xv.x);
                    acc01[n] = ffma2(xp, wk0.x, acc01[n]);
                    acc23[n] = ffma2(xp, wk0.y, acc23[n]);
                    xp = pack2(xv.y);
                    acc01[n] = ffma2(xp, wk1.x, acc01[n]);
                    acc23[n] = ffma2(xp, wk1.y, acc23[n]);
                    xp = pack2(xv.z);
                    acc01[n] = ffma2(xp, wk2.x, acc01[n]);
                    acc23[n] = ffma2(xp, wk2.y, acc23[n]);
                    xp = pack2(xv.w);
                    acc01[n] = ffma2(xp, wk3.x, acc01[n]);
                    acc23[n] = ffma2(xp, wk3.y, acc23[n]);
                }
            }
            #pragma unroll
            for (int n = 0; n < 4; n++) {
                float f0, f1, f2, f3;
                unpack2(acc01[n], f0, f1);
                unpack2(acc23[n], f2, f3);
                float4 h;
                h.x = fmaxf(fmaf(f0, A1v.x, C1v.x), 0.f);
                h.y = fmaxf(fmaf(f1, A1v.y, C1v.y), 0.f);
                h.z = fmaxf(fmaf(f2, A1v.z, C1v.z), 0.f);
                h.w = fmaxf(fmaf(f3, A1v.w, C1v.w), 0.f);
                *(float4*)(hs + (nb + n) * 128 + j1) = h;
            }
        }
        __syncthreads();

        // ---- GEMM2: lane covers j2=(lane&15)*4; half picks 2 of warp's 4 nodes ----
        {
            const int nb = warp * 4 + (lane >> 4) * 2;
            unsigned long long acc01[2], acc23[2];
            #pragma unroll
            for (int n = 0; n < 2; n++) { acc01[n] = 0ULL; acc23[n] = 0ULL; }

            for (int k4 = 0; k4 < 32; k4++) {
                ulonglong2 wk0 = *(const ulonglong2*)(W2s + (k4 * 4 + 0) * 64 + j2);
                ulonglong2 wk1 = *(const ulonglong2*)(W2s + (k4 * 4 + 1) * 64 + j2);
                ulonglong2 wk2 = *(const ulonglong2*)(W2s + (k4 * 4 + 2) * 64 + j2);
                ulonglong2 wk3 = *(const ulonglong2*)(W2s + (k4 * 4 + 3) * 64 + j2);
                #pragma unroll
                for (int n = 0; n < 2; n++) {
                    const float4 hv = *(const float4*)(hs + (nb + n) * 128 + k4 * 4);
                    unsigned long long xp;
                    xp = pack2(hv.x);
                    acc01[n] = ffma2(xp, wk0.x, acc01[n]);
                    acc23[n] = ffma2(xp, wk0.y, acc23[n]);
                    xp = pack2(hv.y);
                    acc01[n] = ffma2(xp, wk1.x, acc01[n]);
                    acc23[n] = ffma2(xp, wk1.y, acc23[n]);
                    xp = pack2(hv.z);
                    acc01[n] = ffma2(xp, wk2.x, acc01[n]);
                    acc23[n] = ffma2(xp, wk2.y, acc23[n]);
                    xp = pack2(hv.w);
                    acc01[n] = ffma2(xp, wk3.x, acc01[n]);
                    acc23[n] = ffma2(xp, wk3.y, acc23[n]);
                }
            }
            #pragma unroll
            for (int n = 0; n < 2; n++) {
                const int node = base + nb + n;
                if (node < NN) {
                    float f0, f1, f2, f3;
                    unpack2(acc01[n], f0, f1);
                    unpack2(acc23[n], f2, f3);
                    float4 o;
                    o.x = fmaxf(fmaf(f0, A2v.x, C2v.x), 0.f);
                    o.y = fmaxf(fmaf(f1, A2v.y, C2v.y), 0.f);
                    o.z = fmaxf(fmaf(f2, A2v.z, C2v.z), 0.f);
                    o.w = fmaxf(fmaf(f3, A2v.w, C2v.w), 0.f);
                    *(float4*)(xout + (size_t)node * 64 + j2) = o;
                }
            }
        }
        __syncthreads();
    }
}

// ---------------------------------------------------------------------------
// Register-tiled head (unchanged).
// ---------------------------------------------------------------------------
#define HEAD_SHM_FLOATS 32960
#define HEAD_SHM_BYTES  (HEAD_SHM_FLOATS * 4)

__global__ __launch_bounds__(512) void head_kernel(
    const float* __restrict__ x,
    const float* __restrict__ lin1_W, const float* __restrict__ lin1_b,
    const float* __restrict__ g,  const float* __restrict__ b,
    const float* __restrict__ m,  const float* __restrict__ v,
    const float* __restrict__ lin2_W, const float* __restrict__ lin2_b,
    float* __restrict__ out)
{
    extern __shared__ float sm[];
    float* W1s = sm;             // [64][64]
    float* W2s = W1s + 4096;     // [64][64] (cols 40..63 zero)
    float* a1  = W2s + 4096;     // [64]
    float* c1  = a1 + 64;        // [64]
    float* c2  = c1 + 64;        // [64]
    float* xs  = c2 + 64;        // [128][64]
    float* ts  = xs + 8192;      // [128][64]
    float* ls  = ts + 8192;      // [128][64]

    const int tid  = threadIdx.x;
    const int warp = tid >> 5;
    const int lane = tid & 31;

    for (int i = tid; i < 4096; i += 512) W1s[i] = lin1_W[i];
    for (int i = tid; i < 4096; i += 512) {
        int col = i & 63;
        W2s[i] = (col < CC) ? lin2_W[(i >> 6) * CC + col] : 0.0f;
    }
    if (tid < 64) {
        float a = g[tid] * rsqrtf(v[tid] + BN_EPS);
        a1[tid] = a;
        c1[tid] = (lin1_b[tid] - m[tid]) * a + b[tid];
    } else if (tid < 128) {
        int j = tid - 64;
        c2[j] = (j < CC) ? lin2_b[j] : 0.0f;
    }
    __syncthreads();

    const int ntiles = (NN + 127) >> 7;
    for (int tile = blockIdx.x; tile < ntiles; tile += gridDim.x) {
        const int base = tile << 7;

        for (int i = tid; i < 2048; i += 512) {
            int node = i >> 4;
            float4 vv;
            if (base + node < NN)
                vv = *(const float4*)(x + (size_t)(base + node) * 64 + (i & 15) * 4);
            else
                vv = make_float4(0.f, 0.f, 0.f, 0.f);
            *(float4*)(xs + i * 4) = vv;
        }
        __syncthreads();

        {
            const int j0 = lane * 2;
            float2 acc[8];
            #pragma unroll
            for (int n = 0; n < 8; n++) acc[n] = make_float2(0.f, 0.f);
            const float* xrow = xs + (warp * 8) * 64;

            for (int k4 = 0; k4 < 16; k4++) {
                const float2 w0 = *(const float2*)(W1s + (k4 * 4 + 0) * 64 + j0);
                const float2 w1 = *(const float2*)(W1s + (k4 * 4 + 1) * 64 + j0);
                const float2 w2 = *(const float2*)(W1s + (k4 * 4 + 2) * 64 + j0);
                const float2 w3 = *(const float2*)(W1s + (k4 * 4 + 3) * 64 + j0);
                #pragma unroll
                for (int n = 0; n < 8; n++) {
                    const float4 xv = *(const float4*)(xrow + n * 64 + k4 * 4);
                    acc[n].x = fmaf(xv.x, w0.x, acc[n].x);
                    acc[n].y = fmaf(xv.x, w0.y, acc[n].y);
                    acc[n].x = fmaf(xv.y, w1.x, acc[n].x);
                    acc[n].y = fmaf(xv.y, w1.y, acc[n].y);
                    acc[n].x = fmaf(xv.z, w2.x, acc[n].x);
                    acc[n].y = fmaf(xv.z, w2.y, acc[n].y);
                    acc[n].x = fmaf(xv.w, w3.x, acc[n].x);
                    acc[n].y = fmaf(xv.w, w3.y, acc[n].y);
                }
            }
            const float A0 = a1[j0], A1 = a1[j0 + 1];
            const float C0 = c1[j0], C1 = c1[j0 + 1];
            #pragma unroll
            for (int n = 0; n < 8; n++) {
                float2 t;
                t.x = fmaxf(fmaf(acc[n].x, A0, C0), 0.f);
                t.y = fmaxf(fmaf(acc[n].y, A1, C1), 0.f);
                *(float2*)(ts + (warp * 8 + n) * 64 + j0) = t;
            }
        }
        __syncthreads();

        {
            const int j0 = lane * 2;
            float2 acc[8];
            #pragma unroll
            for (int n = 0; n < 8; n++) acc[n] = make_float2(0.f, 0.f);
            const float* trow = ts + (warp * 8) * 64;

            for (int k4 = 0; k4 < 16; k4++) {
                const float2 w0 = *(const float2*)(W2s + (k4 * 4 + 0) * 64 + j0);
                const float2 w1 = *(const float2*)(W2s + (k4 * 4 + 1) * 64 + j0);
                const float2 w2 = *(const float2*)(W2s + (k4 * 4 + 2) * 64 + j0);
                const float2 w3 = *(const float2*)(W2s + (k4 * 4 + 3) * 64 + j0);
                #pragma unroll
                for (int n = 0; n < 8; n++) {
                    const float4 tv = *(const float4*)(trow + n * 64 + k4 * 4);
                    acc[n].x = fmaf(tv.x, w0.x, acc[n].x);
                    acc[n].y = fmaf(tv.x, w0.y, acc[n].y);
                    acc[n].x = fmaf(tv.y, w1.x, acc[n].x);
                    acc[n].y = fmaf(tv.y, w1.y, acc[n].y);
                    acc[n].x = fmaf(tv.z, w2.x, acc[n].x);
                    acc[n].y = fmaf(tv.z, w2.y, acc[n].y);
                    acc[n].x = fmaf(tv.w, w3.x, acc[n].x);
                    acc[n].y = fmaf(tv.w, w3.y, acc[n].y);
                }
            }
            const float C0 = c2[j0], C1 = c2[j0 + 1];
            #pragma unroll
            for (int n = 0; n < 8; n++) {
                float2 o;
                o.x = acc[n].x + C0;
                o.y = acc[n].y + C1;
                *(float2*)(ls + (warp * 8 + n) * 64 + j0) = o;
            }
        }
        __syncthreads();

        for (int n = 0; n < 8; n++) {
            const int node = base + warp * 8 + n;
            if (node >= NN) break;
            const float* lr = ls + (warp * 8 + n) * 64;
            float v0 = lr[lane];
            float v1 = (lane < CC - 32) ? lr[32 + lane] : -3.0e38f;
            float mx = fmaxf(v0, v1);
            #pragma unroll
            for (int o = 16; o > 0; o >>= 1)
                mx = fmaxf(mx, __shfl_xor_sync(0xffffffffu, mx, o));
            float s = expf(v0 - mx) + ((lane < CC - 32) ? expf(v1 - mx) : 0.f);
            #pragma unroll
            for (int o = 16; o > 0; o >>= 1)
                s += __shfl_xor_sync(0xffffffffu, s, o);
            const float lse = mx + logf(s);
            float* orow = out + (size_t)node * CC;
            orow[lane] = v0 - lse;
            if (lane < CC - 32) orow[32 + lane] = v1 - lse;
        }
        __syncthreads();
    }
}

// ---------------------------------------------------------------------------
extern "C" void kernel_launch(void* const* d_in, const int* in_sizes, int n_in,
                              void* d_out, int out_size) {
    const float* x = nullptr;
    const void*  ei = nullptr;
    const float* w24[2] = {nullptr, nullptr}; int n24 = 0;
    const float* p384[5] = {0};               int n384 = 0;
    const float* p192[5] = {0};               int n192 = 0;
    const float* p64[5]  = {0};               int n64 = 0;
    const float* lin1_W = nullptr;
    const float* lin2_W = nullptr;
    const float* lin2_b = nullptr;

    for (int i = 0; i < n_in; i++) {
        int s = in_sizes[i];
        const float* p = (const float*)d_in[i];
        if      (s == NN * FF)     x = p;
        else if (s == 2 * EE)      ei = d_in[i];
        else if (s == LL * FF * H2) { if (n24 < 2) w24[n24++] = p; }
        else if (s == LL * H2)     { if (n384 < 5) p384[n384++] = p; }
        else if (s == LL * HH)     { if (n192 < 5) p192[n192++] = p; }
        else if (s == HH * HH)     lin1_W = p;
        else if (s == HH)          { if (n64 < 5) p64[n64++] = p; }
        else if (s == HH * CC)     lin2_W = p;
        else if (s == CC)          lin2_b = p;
    }

    const float* W1s  = w24[0];
    const float* W2s  = w24[1];
    const float* b1s  = p384[0], *g1s = p384[1], *bt1s = p384[2],
               * m1s  = p384[3], *v1s = p384[4];
    const float* b2s  = p192[0], *gcs = p192[1], *bcs = p192[2],
               * mcs  = p192[3], *vcs = p192[4];
    const float* lin1_b = p64[0], *g_bn1 = p64[1], *b_bn1 = p64[2],
               * m_bn1  = p64[3], *v_bn1 = p64[4];

    if (!x || !ei || !W1s || !W2s || !lin1_W || !lin2_W || !lin2_b) return;

    float* gx;   cudaGetSymbolAddress((void**)&gx,   g_x);
    float* gagg; cudaGetSymbolAddress((void**)&gagg, g_agg);
    int*   gdeg; cudaGetSymbolAddress((void**)&gdeg, g_deg);

    cudaFuncSetAttribute(mlp_kernel,  cudaFuncAttributeMaxDynamicSharedMemorySize, MLP_SHM_BYTES);
    cudaFuncSetAttribute(head_kernel, cudaFuncAttributeMaxDynamicSharedMemorySize, HEAD_SHM_BYTES);

    detect_kernel<<<1, 256>>>((const long long*)ei);
    cudaMemsetAsync(gdeg, 0, NN * sizeof(int));
    fill_kernel<<<(EE + 255) / 256, 256>>>(ei);

    const int gather_blocks = (NN * 32 + 255) / 256;

    const float* cur = x;
    for (int l = 0; l < LL; l++) {
        gather_kernel<<<gather_blocks, 256>>>(cur, gagg);
        mlp_kernel<<<296, 512, MLP_SHM_BYTES>>>(   // 2 blocks/SM
            gagg,
            W1s + (size_t)l * FF * H2,  b1s + (size_t)l * H2,
            g1s + (size_t)l * H2,       bt1s + (size_t)l * H2,
            m1s + (size_t)l * H2,       v1s + (size_t)l * H2,
            W2s + (size_t)l * H2 * HH,  b2s + (size_t)l * HH,
            gcs + (size_t)l * HH,       bcs + (size_t)l * HH,
            mcs + (size_t)l * HH,       vcs + (size_t)l * HH,
            gx);
        cur = gx;
    }

    head_kernel<<<148, 512, HEAD_SHM_BYTES>>>(
        gx, lin1_W, lin1_b, g_bn1, b_bn1, m_bn1, v_bn1, lin2_W, lin2_b,
        (float*)d_out);
}

// round 14
// speedup vs baseline: 1.1621x; 1.1605x over previous
#include <cuda_runtime.h>
#include <cstdint>

#define NN 50000
#define EE 800000
#define FF 64
#define HH 64
#define H2 128
#define CC 40
#define LL 3
#define BN_EPS 1e-5f
#define MAXDEG 128

__device__ __align__(16) float g_x[NN * FF];
__device__ __align__(16) float g_agg[NN * FF];
__device__ int g_is32;

// direct-slot CSR
__device__ int g_deg[NN];
__device__ int g_colidx[NN * MAXDEG];

// ---------------------------------------------------------------------------
// f32x2 helpers (sm_103a packed dual-fp32)
// ---------------------------------------------------------------------------
__device__ __forceinline__ unsigned long long ffma2(
    unsigned long long a, unsigned long long b, unsigned long long c) {
    unsigned long long d;
    asm("fma.rn.f32x2 %0, %1, %2, %3;" : "=l"(d) : "l"(a), "l"(b), "l"(c));
    return d;
}
__device__ __forceinline__ unsigned long long pack2(float v) {
    unsigned long long d;
    unsigned int u = __float_as_uint(v);
    asm("mov.b64 %0, {%1, %2};" : "=l"(d) : "r"(u), "r"(u));
    return d;
}
__device__ __forceinline__ void unpack2(unsigned long long d, float& lo, float& hi) {
    unsigned int a, b;
    asm("mov.b64 {%0, %1}, %2;" : "=r"(a), "=r"(b) : "l"(d));
    lo = __uint_as_float(a);
    hi = __uint_as_float(b);
}

// ---------------------------------------------------------------------------
__global__ void detect_kernel(const long long* __restrict__ ei) {
    long long v = ei[threadIdx.x];
    int bad = (v < 0 || v >= NN) ? 1 : 0;
    int any = __syncthreads_or(bad);
    if (threadIdx.x == 0) g_is32 = any;
}

__global__ void fill_kernel(const void* __restrict__ ei) {
    int e = blockIdx.x * blockDim.x + threadIdx.x;
    if (e >= EE) return;
    int src, dst;
    if (g_is32) {
        src = __ldg((const int*)ei + e);
        dst = __ldg((const int*)ei + EE + e);
    } else {
        src = (int)__ldg((const long long*)ei + e);
        dst = (int)__ldg((const long long*)ei + EE + e);
    }
    if ((unsigned)src >= NN || (unsigned)dst >= NN) return;
    int pos = atomicAdd(&g_deg[dst], 1);
    if (pos < MAXDEG) g_colidx[dst * MAXDEG + pos] = src;
}

// ---------------------------------------------------------------------------
// CSR gather (unchanged).
// ---------------------------------------------------------------------------
__global__ __launch_bounds__(256) void gather_kernel(
    const float* __restrict__ x, float* __restrict__ agg)
{
    const int warp = (blockIdx.x * blockDim.x + threadIdx.x) >> 5;
    if (warp >= NN) return;
    const int lane = threadIdx.x & 31;
    const int half = lane >> 4;
    const int sub  = lane & 15;

    const int start = warp * MAXDEG;
    const int end   = start + min(g_deg[warp], MAXDEG);

    float4 acc = make_float4(0.f, 0.f, 0.f, 0.f);
    if (half == 0)
        acc = *(const float4*)(x + (size_t)warp * 64 + sub * 4);

    int k = start + half;
    for (; k + 6 < end; k += 8) {
        const int i0 = __ldg(g_colidx + k);
        const int i1 = __ldg(g_colidx + k + 2);
        const int i2 = __ldg(g_colidx + k + 4);
        const int i3 = __ldg(g_colidx + k + 6);
        const float4 v0 = *(const float4*)(x + (size_t)i0 * 64 + sub * 4);
        const float4 v1 = *(const float4*)(x + (size_t)i1 * 64 + sub * 4);
        const float4 v2 = *(const float4*)(x + (size_t)i2 * 64 + sub * 4);
        const float4 v3 = *(const float4*)(x + (size_t)i3 * 64 + sub * 4);
        acc.x += v0.x + v1.x + v2.x + v3.x;
        acc.y += v0.y + v1.y + v2.y + v3.y;
        acc.z += v0.z + v1.z + v2.z + v3.z;
        acc.w += v0.w + v1.w + v2.w + v3.w;
    }
    for (; k < end; k += 2) {
        const int i = __ldg(g_colidx + k);
        const float4 v = *(const float4*)(x + (size_t)i * 64 + sub * 4);
        acc.x += v.x; acc.y += v.y; acc.z += v.z; acc.w += v.w;
    }

    acc.x += __shfl_xor_sync(0xffffffffu, acc.x, 16);
    acc.y += __shfl_xor_sync(0xffffffffu, acc.y, 16);
    acc.z += __shfl_xor_sync(0xffffffffu, acc.z, 16);
    acc.w += __shfl_xor_sync(0xffffffffu, acc.w, 16);

    if (half == 0)
        *(float4*)(agg + (size_t)warp * 64 + sub * 4) = acc;
}

// ---------------------------------------------------------------------------
// FFMA2 MLP — exact R11 mapping (512 thr, 128-node tile, 8 nodes/warp,
// 16 warps/SM) + software-pipelined tile loads:
//   GEMM1 also issues next tile's LDGs into 16 regs; after the hs-barrier,
//   GEMM2 overlaps with the register->xs store. 2 barriers/tile (was 3),
//   global-load latency hidden.
// smem floats: W1 8192 + W2 8192 + a1/c1 256 + a2/c2 128 + xs 8192 + hs 16384
//            = 41344 (165,376 B; 1 block/SM).
// ---------------------------------------------------------------------------
#define MLP_SHM_FLOATS 41344
#define MLP_SHM_BYTES  (MLP_SHM_FLOATS * 4)

__global__ __launch_bounds__(512) void mlp_kernel(
    const float* __restrict__ hin,
    const float* __restrict__ W1, const float* __restrict__ b1,
    const float* __restrict__ g1, const float* __restrict__ bt1,
    const float* __restrict__ m1, const float* __restrict__ v1,
    const float* __restrict__ W2, const float* __restrict__ b2,
    const float* __restrict__ gc, const float* __restrict__ bc,
    const float* __restrict__ mc, const float* __restrict__ vc,
    float* __restrict__ xout)
{
    extern __shared__ float sm[];
    float* W1s = sm;             // [64][128]   8192
    float* W2s = W1s + 8192;     // [128][64]   8192
    float* a1  = W2s + 8192;     // [128]
    float* c1  = a1 + 128;       // [128]
    float* a2  = c1 + 128;       // [64]
    float* c2  = a2 + 64;        // [64]
    float* xs  = c2 + 64;        // [128][64]   8192
    float* hs  = xs + 8192;      // [128][128]  16384

    const int tid  = threadIdx.x;
    const int warp = tid >> 5;
    const int lane = tid & 31;

    for (int i = tid; i < 8192; i += 512) W1s[i] = W1[i];
    for (int i = tid; i < 8192; i += 512) W2s[i] = W2[i];
    if (tid < 128) {
        float a = g1[tid] * rsqrtf(v1[tid] + BN_EPS);
        a1[tid] = a;
        c1[tid] = (b1[tid] - m1[tid]) * a + bt1[tid];
    } else if (tid < 192) {
        int j = tid - 128;
        float a = gc[j] * rsqrtf(vc[j] + BN_EPS);
        a2[j] = a;
        c2[j] = (b2[j] - mc[j]) * a + bc[j];
    }

    const int ntiles = (NN + 127) >> 7;

    // ---- prefetch first tile into registers, store to xs ----
    float4 pf[4];
    {
        const int tile0 = blockIdx.x;
        const int base  = tile0 << 7;
        #pragma unroll
        for (int k = 0; k < 4; k++) {
            const int i = tid + k * 512;     // i in [0, 2048)
            const int node = i >> 4;
            if (tile0 < ntiles && base + node < NN)
                pf[k] = *(const float4*)(hin + (size_t)(base + node) * 64 + (i & 15) * 4);
            else
                pf[k] = make_float4(0.f, 0.f, 0.f, 0.f);
        }
        #pragma unroll
        for (int k = 0; k < 4; k++) {
            const int i = tid + k * 512;
            *(float4*)(xs + i * 4) = pf[k];
        }
    }
    __syncthreads();   // xs(tile0) ready + W/consts ready

    for (int tile = blockIdx.x; tile < ntiles; tile += gridDim.x) {
        const int base = tile << 7;
        const int next = tile + gridDim.x;

        // ---- GEMM1: [128x64] @ [64x128] -> hs, bn+relu ----
        {
            const int j0 = lane * 4;
            unsigned long long acc01[8], acc23[8];
            #pragma unroll
            for (int n = 0; n < 8; n++) { acc01[n] = 0ULL; acc23[n] = 0ULL; }
            const float* xrow = xs + (warp * 8) * 64;

            for (int k4 = 0; k4 < 16; k4++) {
                ulonglong2 wk0 = *(const ulonglong2*)(W1s + (k4 * 4 + 0) * 128 + j0);
                ulonglong2 wk1 = *(const ulonglong2*)(W1s + (k4 * 4 + 1) * 128 + j0);
                ulonglong2 wk2 = *(const ulonglong2*)(W1s + (k4 * 4 + 2) * 128 + j0);
                ulonglong2 wk3 = *(const ulonglong2*)(W1s + (k4 * 4 + 3) * 128 + j0);
                #pragma unroll
                for (int n = 0; n < 8; n++) {
                    const float4 xv = *(const float4*)(xrow + n * 64 + k4 * 4);
                    unsigned long long xp;
                    xp = pack2(xv.x);
                    acc01[n] = ffma2(xp, wk0.x, acc01[n]);
                    acc23[n] = ffma2(xp, wk0.y, acc23[n]);
                    xp = pack2(xv.y);
                    acc01[n] = ffma2(xp, wk1.x, acc01[n]);
                    acc23[n] = ffma2(xp, wk1.y, acc23[n]);
                    xp = pack2(xv.z);
                    acc01[n] = ffma2(xp, wk2.x, acc01[n]);
                    acc23[n] = ffma2(xp, wk2.y, acc23[n]);
                    xp = pack2(xv.w);
                    acc01[n] = ffma2(xp, wk3.x, acc01[n]);
                    acc23[n] = ffma2(xp, wk3.y, acc23[n]);
                }
            }
            const float4 A = *(const float4*)(a1 + j0);
            const float4 C = *(const float4*)(c1 + j0);
            #pragma unroll
            for (int n = 0; n < 8; n++) {
                float f0, f1, f2, f3;
                unpack2(acc01[n], f0, f1);
                unpack2(acc23[n], f2, f3);
                float4 h;
                h.x = fmaxf(fmaf(f0, A.x, C.x), 0.f);
                h.y = fmaxf(fmaf(f1, A.y, C.y), 0.f);
                h.z = fmaxf(fmaf(f2, A.z, C.z), 0.f);
                h.w = fmaxf(fmaf(f3, A.w, C.w), 0.f);
                *(float4*)(hs + (warp * 8 + n) * 128 + j0) = h;
            }
        }

        // ---- issue next tile's global loads (latency hidden by sync+GEMM2)
        if (next < ntiles) {
            const int nbase = next << 7;
            #pragma unroll
            for (int k = 0; k < 4; k++) {
                const int i = tid + k * 512;
                const int node = i >> 4;
                if (nbase + node < NN)
                    pf[k] = *(const float4*)(hin + (size_t)(nbase + node) * 64 + (i & 15) * 4);
                else
                    pf[k] = make_float4(0.f, 0.f, 0.f, 0.f);
            }
        }
        __syncthreads();   // hs ready; xs fully consumed

        // ---- GEMM2: [128x128] @ [128x64] -> xout, bn+relu ----
        {
            const int j0 = lane * 2;
            float2 acc[8];
            #pragma unroll
            for (int n = 0; n < 8; n++) acc[n] = make_float2(0.f, 0.f);
            const float* hrow = hs + (warp * 8) * 128;

            for (int k4 = 0; k4 < 32; k4++) {
                const float2 w0 = *(const float2*)(W2s + (k4 * 4 + 0) * 64 + j0);
                const float2 w1 = *(const float2*)(W2s + (k4 * 4 + 1) * 64 + j0);
                const float2 w2 = *(const float2*)(W2s + (k4 * 4 + 2) * 64 + j0);
                const float2 w3 = *(const float2*)(W2s + (k4 * 4 + 3) * 64 + j0);
                #pragma unroll
                for (int n = 0; n < 8; n++) {
                    const float4 hv = *(const float4*)(hrow + n * 128 + k4 * 4);
                    acc[n].x = fmaf(hv.x, w0.x, acc[n].x);
                    acc[n].y = fmaf(hv.x, w0.y, acc[n].y);
                    acc[n].x = fmaf(hv.y, w1.x, acc[n].x);
                    acc[n].y = fmaf(hv.y, w1.y, acc[n].y);
                    acc[n].x = fmaf(hv.z, w2.x, acc[n].x);
                    acc[n].y = fmaf(hv.z, w2.y, acc[n].y);
                    acc[n].x = fmaf(hv.w, w3.x, acc[n].x);
                    acc[n].y = fmaf(hv.w, w3.y, acc[n].y);
                }
            }
            const float A0 = a2[j0], A1 = a2[j0 + 1];
            const float C0 = c2[j0], C1 = c2[j0 + 1];
            #pragma unroll
            for (int n = 0; n < 8; n++) {
                const int node = base + warp * 8 + n;
                if (node < NN) {
                    float2 o;
                    o.x = fmaxf(fmaf(acc[n].x, A0, C0), 0.f);
                    o.y = fmaxf(fmaf(acc[n].y, A1, C1), 0.f);
                    *(float2*)(xout + (size_t)node * 64 + j0) = o;
                }
            }
        }

        // ---- store prefetched tile into xs (xs free since last barrier) ----
        if (next < ntiles) {
            #pragma unroll
            for (int k = 0; k < 4; k++) {
                const int i = tid + k * 512;
                *(float4*)(xs + i * 4) = pf[k];
            }
        }
        __syncthreads();   // xs(next) ready; hs free for next GEMM1
    }
}

// ---------------------------------------------------------------------------
// Register-tiled head (unchanged).
// ---------------------------------------------------------------------------
#define HEAD_SHM_FLOATS 32960
#define HEAD_SHM_BYTES  (HEAD_SHM_FLOATS * 4)

__global__ __launch_bounds__(512) void head_kernel(
    const float* __restrict__ x,
    const float* __restrict__ lin1_W, const float* __restrict__ lin1_b,
    const float* __restrict__ g,  const float* __restrict__ b,
    const float* __restrict__ m,  const float* __restrict__ v,
    const float* __restrict__ lin2_W, const float* __restrict__ lin2_b,
    float* __restrict__ out)
{
    extern __shared__ float sm[];
    float* W1s = sm;             // [64][64]
    float* W2s = W1s + 4096;     // [64][64] (cols 40..63 zero)
    float* a1  = W2s + 4096;     // [64]
    float* c1  = a1 + 64;        // [64]
    float* c2  = c1 + 64;        // [64]
    float* xs  = c2 + 64;        // [128][64]
    float* ts  = xs + 8192;      // [128][64]
    float* ls  = ts + 8192;      // [128][64]

    const int tid  = threadIdx.x;
    const int warp = tid >> 5;
    const int lane = tid & 31;

    for (int i = tid; i < 4096; i += 512) W1s[i] = lin1_W[i];
    for (int i = tid; i < 4096; i += 512) {
        int col = i & 63;
        W2s[i] = (col < CC) ? lin2_W[(i >> 6) * CC + col] : 0.0f;
    }
    if (tid < 64) {
        float a = g[tid] * rsqrtf(v[tid] + BN_EPS);
        a1[tid] = a;
        c1[tid] = (lin1_b[tid] - m[tid]) * a + b[tid];
    } else if (tid < 128) {
        int j = tid - 64;
        c2[j] = (j < CC) ? lin2_b[j] : 0.0f;
    }
    __syncthreads();

    const int ntiles = (NN + 127) >> 7;
    for (int tile = blockIdx.x; tile < ntiles; tile += gridDim.x) {
        const int base = tile << 7;

        for (int i = tid; i < 2048; i += 512) {
            int node = i >> 4;
            float4 vv;
            if (base + node < NN)
                vv = *(const float4*)(x + (size_t)(base + node) * 64 + (i & 15) * 4);
            else
                vv = make_float4(0.f, 0.f, 0.f, 0.f);
            *(float4*)(xs + i * 4) = vv;
        }
        __syncthreads();

        {
            const int j0 = lane * 2;
            float2 acc[8];
            #pragma unroll
            for (int n = 0; n < 8; n++) acc[n] = make_float2(0.f, 0.f);
            const float* xrow = xs + (warp * 8) * 64;

            for (int k4 = 0; k4 < 16; k4++) {
                const float2 w0 = *(const float2*)(W1s + (k4 * 4 + 0) * 64 + j0);
                const float2 w1 = *(const float2*)(W1s + (k4 * 4 + 1) * 64 + j0);
                const float2 w2 = *(const float2*)(W1s + (k4 * 4 + 2) * 64 + j0);
                const float2 w3 = *(const float2*)(W1s + (k4 * 4 + 3) * 64 + j0);
                #pragma unroll
                for (int n = 0; n < 8; n++) {
                    const float4 xv = *(const float4*)(xrow + n * 64 + k4 * 4);
                    acc[n].x = fmaf(xv.x, w0.x, acc[n].x);
                    acc[n].y = fmaf(xv.x, w0.y, acc[n].y);
                    acc[n].x = fmaf(xv.y, w1.x, acc[n].x);
                    acc[n].y = fmaf(xv.y, w1.y, acc[n].y);
                    acc[n].x = fmaf(xv.z, w2.x, acc[n].x);
                    acc[n].y = fmaf(xv.z, w2.y, acc[n].y);
                    acc[n].x = fmaf(xv.w, w3.x, acc[n].x);
                    acc[n].y = fmaf(xv.w, w3.y, acc[n].y);
                }
            }
            const float A0 = a1[j0], A1 = a1[j0 + 1];
            const float C0 = c1[j0], C1 = c1[j0 + 1];
            #pragma unroll
            for (int n = 0; n < 8; n++) {
                float2 t;
                t.x = fmaxf(fmaf(acc[n].x, A0, C0), 0.f);
                t.y = fmaxf(fmaf(acc[n].y, A1, C1), 0.f);
                *(float2*)(ts + (warp * 8 + n) * 64 + j0) = t;
            }
        }
        __syncthreads();

        {
            const int j0 = lane * 2;
            float2 acc[8];
            #pragma unroll
            for (int n = 0; n < 8; n++) acc[n] = make_float2(0.f, 0.f);
            const float* trow = ts + (warp * 8) * 64;

            for (int k4 = 0; k4 < 16; k4++) {
                const float2 w0 = *(const float2*)(W2s + (k4 * 4 + 0) * 64 + j0);
                const float2 w1 = *(const float2*)(W2s + (k4 * 4 + 1) * 64 + j0);
                const float2 w2 = *(const float2*)(W2s + (k4 * 4 + 2) * 64 + j0);
                const float2 w3 = *(const float2*)(W2s + (k4 * 4 + 3) * 64 + j0);
                #pragma unroll
                for (int n = 0; n < 8; n++) {
                    const float4 tv = *(const float4*)(trow + n * 64 + k4 * 4);
                    acc[n].x = fmaf(tv.x, w0.x, acc[n].x);
                    acc[n].y = fmaf(tv.x, w0.y, acc[n].y);
                    acc[n].x = fmaf(tv.y, w1.x, acc[n].x);
                    acc[n].y = fmaf(tv.y, w1.y, acc[n].y);
                    acc[n].x = fmaf(tv.z, w2.x, acc[n].x);
                    acc[n].y = fmaf(tv.z, w2.y, acc[n].y);
                    acc[n].x = fmaf(tv.w, w3.x, acc[n].x);
                    acc[n].y = fmaf(tv.w, w3.y, acc[n].y);
                }
            }
            const float C0 = c2[j0], C1 = c2[j0 + 1];
            #pragma unroll
            for (int n = 0; n < 8; n++) {
                float2 o;
                o.x = acc[n].x + C0;
                o.y = acc[n].y + C1;
                *(float2*)(ls + (warp * 8 + n) * 64 + j0) = o;
            }
        }
        __syncthreads();

        for (int n = 0; n < 8; n++) {
            const int node = base + warp * 8 + n;
            if (node >= NN) break;
            const float* lr = ls + (warp * 8 + n) * 64;
            float v0 = lr[lane];
            float v1 = (lane < CC - 32) ? lr[32 + lane] : -3.0e38f;
            float mx = fmaxf(v0, v1);
            #pragma unroll
            for (int o = 16; o > 0; o >>= 1)
                mx = fmaxf(mx, __shfl_xor_sync(0xffffffffu, mx, o));
            float s = expf(v0 - mx) + ((lane < CC - 32) ? expf(v1 - mx) : 0.f);
            #pragma unroll
            for (int o = 16; o > 0; o >>= 1)
                s += __shfl_xor_sync(0xffffffffu, s, o);
            const float lse = mx + logf(s);
            float* orow = out + (size_t)node * CC;
            orow[lane] = v0 - lse;
            if (lane < CC - 32) orow[32 + lane] = v1 - lse;
        }
        __syncthreads();
    }
}

// ---------------------------------------------------------------------------
extern "C" void kernel_launch(void* const* d_in, const int* in_sizes, int n_in,
                              void* d_out, int out_size) {
    const float* x = nullptr;
    const void*  ei = nullptr;
    const float* w24[2] = {nullptr, nullptr}; int n24 = 0;
    const float* p384[5] = {0};               int n384 = 0;
    const float* p192[5] = {0};               int n192 = 0;
    const float* p64[5]  = {0};               int n64 = 0;
    const float* lin1_W = nullptr;
    const float* lin2_W = nullptr;
    const float* lin2_b = nullptr;

    for (int i = 0; i < n_in; i++) {
        int s = in_sizes[i];
        const float* p = (const float*)d_in[i];
        if      (s == NN * FF)     x = p;
        else if (s == 2 * EE)      ei = d_in[i];
        else if (s == LL * FF * H2) { if (n24 < 2) w24[n24++] = p; }
        else if (s == LL * H2)     { if (n384 < 5) p384[n384++] = p; }
        else if (s == LL * HH)     { if (n192 < 5) p192[n192++] = p; }
        else if (s == HH * HH)     lin1_W = p;
        else if (s == HH)          { if (n64 < 5) p64[n64++] = p; }
        else if (s == HH * CC)     lin2_W = p;
        else if (s == CC)          lin2_b = p;
    }

    const float* W1s  = w24[0];
    const float* W2s  = w24[1];
    const float* b1s  = p384[0], *g1s = p384[1], *bt1s = p384[2],
               * m1s  = p384[3], *v1s = p384[4];
    const float* b2s  = p192[0], *gcs = p192[1], *bcs = p192[2],
               * mcs  = p192[3], *vcs = p192[4];
    const float* lin1_b = p64[0], *g_bn1 = p64[1], *b_bn1 = p64[2],
               * m_bn1  = p64[3], *v_bn1 = p64[4];

    if (!x || !ei || !W1s || !W2s || !lin1_W || !lin2_W || !lin2_b) return;

    float* gx;   cudaGetSymbolAddress((void**)&gx,   g_x);
    float* gagg; cudaGetSymbolAddress((void**)&gagg, g_agg);
    int*   gdeg; cudaGetSymbolAddress((void**)&gdeg, g_deg);

    cudaFuncSetAttribute(mlp_kernel,  cudaFuncAttributeMaxDynamicSharedMemorySize, MLP_SHM_BYTES);
    cudaFuncSetAttribute(head_kernel, cudaFuncAttributeMaxDynamicSharedMemorySize, HEAD_SHM_BYTES);

    detect_kernel<<<1, 256>>>((const long long*)ei);
    cudaMemsetAsync(gdeg, 0, NN * sizeof(int));
    fill_kernel<<<(EE + 255) / 256, 256>>>(ei);

    const int gather_blocks = (NN * 32 + 255) / 256;

    const float* cur = x;
    for (int l = 0; l < LL; l++) {
        gather_kernel<<<gather_blocks, 256>>>(cur, gagg);
        mlp_kernel<<<148, 512, MLP_SHM_BYTES>>>(
            gagg,
            W1s + (size_t)l * FF * H2,  b1s + (size_t)l * H2,
            g1s + (size_t)l * H2,       bt1s + (size_t)l * H2,
            m1s + (size_t)l * H2,       v1s + (size_t)l * H2,
            W2s + (size_t)l * H2 * HH,  b2s + (size_t)l * HH,
            gcs + (size_t)l * HH,       bcs + (size_t)l * HH,
            mcs + (size_t)l * HH,       vcs + (size_t)l * HH,
            gx);
        cur = gx;
    }

    head_kernel<<<148, 512, HEAD_SHM_BYTES>>>(
        gx, lin1_W, lin1_b, g_bn1, b_bn1, m_bn1, v_bn1, lin2_W, lin2_b,
        (float*)d_out);
}

// round 15
// speedup vs baseline: 1.2334x; 1.0614x over previous
#include <cuda_runtime.h>
#include <cstdint>

#define NN 50000
#define EE 800000
#define FF 64
#define HH 64
#define H2 128
#define CC 40
#define LL 3
#define BN_EPS 1e-5f
#define MAXDEG 128

__device__ __align__(16) float g_x[NN * FF];
__device__ __align__(16) float g_agg[NN * FF];
__device__ int g_is32;

// direct-slot CSR
__device__ int g_deg[NN];
__device__ int g_colidx[NN * MAXDEG];

// ---------------------------------------------------------------------------
// f32x2 helpers (sm_103a packed dual-fp32)
// ---------------------------------------------------------------------------
__device__ __forceinline__ unsigned long long ffma2(
    unsigned long long a, unsigned long long b, unsigned long long c) {
    unsigned long long d;
    asm("fma.rn.f32x2 %0, %1, %2, %3;" : "=l"(d) : "l"(a), "l"(b), "l"(c));
    return d;
}
__device__ __forceinline__ unsigned long long pack2(float v) {
    unsigned long long d;
    unsigned int u = __float_as_uint(v);
    asm("mov.b64 %0, {%1, %2};" : "=l"(d) : "r"(u), "r"(u));
    return d;
}
__device__ __forceinline__ void unpack2(unsigned long long d, float& lo, float& hi) {
    unsigned int a, b;
    asm("mov.b64 {%0, %1}, %2;" : "=r"(a), "=r"(b) : "l"(d));
    lo = __uint_as_float(a);
    hi = __uint_as_float(b);
}

// ---------------------------------------------------------------------------
__global__ void detect_kernel(const long long* __restrict__ ei) {
    long long v = ei[threadIdx.x];
    int bad = (v < 0 || v >= NN) ? 1 : 0;
    int any = __syncthreads_or(bad);
    if (threadIdx.x == 0) g_is32 = any;
}

__global__ void fill_kernel(const void* __restrict__ ei) {
    int e = blockIdx.x * blockDim.x + threadIdx.x;
    if (e >= EE) return;
    int src, dst;
    if (g_is32) {
        src = __ldg((const int*)ei + e);
        dst = __ldg((const int*)ei + EE + e);
    } else {
        src = (int)__ldg((const long long*)ei + e);
        dst = (int)__ldg((const long long*)ei + EE + e);
    }
    if ((unsigned)src >= NN || (unsigned)dst >= NN) return;
    int pos = atomicAdd(&g_deg[dst], 1);
    if (pos < MAXDEG) g_colidx[dst * MAXDEG + pos] = src;
}

// ---------------------------------------------------------------------------
// CSR gather (unchanged).
// ---------------------------------------------------------------------------
__global__ __launch_bounds__(256) void gather_kernel(
    const float* __restrict__ x, float* __restrict__ agg)
{
    const int warp = (blockIdx.x * blockDim.x + threadIdx.x) >> 5;
    if (warp >= NN) return;
    const int lane = threadIdx.x & 31;
    const int half = lane >> 4;
    const int sub  = lane & 15;

    const int start = warp * MAXDEG;
    const int end   = start + min(g_deg[warp], MAXDEG);

    float4 acc = make_float4(0.f, 0.f, 0.f, 0.f);
    if (half == 0)
        acc = *(const float4*)(x + (size_t)warp * 64 + sub * 4);

    int k = start + half;
    for (; k + 6 < end; k += 8) {
        const int i0 = __ldg(g_colidx + k);
        const int i1 = __ldg(g_colidx + k + 2);
        const int i2 = __ldg(g_colidx + k + 4);
        const int i3 = __ldg(g_colidx + k + 6);
        const float4 v0 = *(const float4*)(x + (size_t)i0 * 64 + sub * 4);
        const float4 v1 = *(const float4*)(x + (size_t)i1 * 64 + sub * 4);
        const float4 v2 = *(const float4*)(x + (size_t)i2 * 64 + sub * 4);
        const float4 v3 = *(const float4*)(x + (size_t)i3 * 64 + sub * 4);
        acc.x += v0.x + v1.x + v2.x + v3.x;
        acc.y += v0.y + v1.y + v2.y + v3.y;
        acc.z += v0.z + v1.z + v2.z + v3.z;
        acc.w += v0.w + v1.w + v2.w + v3.w;
    }
    for (; k < end; k += 2) {
        const int i = __ldg(g_colidx + k);
        const float4 v = *(const float4*)(x + (size_t)i * 64 + sub * 4);
        acc.x += v.x; acc.y += v.y; acc.z += v.z; acc.w += v.w;
    }

    acc.x += __shfl_xor_sync(0xffffffffu, acc.x, 16);
    acc.y += __shfl_xor_sync(0xffffffffu, acc.y, 16);
    acc.z += __shfl_xor_sync(0xffffffffu, acc.z, 16);
    acc.w += __shfl_xor_sync(0xffffffffu, acc.w, 16);

    if (half == 0)
        *(float4*)(agg + (size_t)warp * 64 + sub * 4) = acc;
}

// ---------------------------------------------------------------------------
// Barrier-free FFMA2 MLP.
// Each warp owns 8-node groups end-to-end: load x -> GEMM1 -> GEMM2 -> store,
// using PRIVATE smem slices (xs_w 8x64, hs_w 8x128). Only __syncwarp()s inside
// the loop; the single __syncthreads() is for the weight staging. Warps slide
// independently: no convoy, GEMM phases overlap across warps.
// NN == 6250*8 exactly -> no node-boundary guards anywhere.
// smem floats: W1 8192 + W2 8192 + a1/c1 256 + a2/c2 128 + xs 8192 + hs 16384
//            = 41344 (165,376 B; 1 block/SM, 16 warps).
// ---------------------------------------------------------------------------
#define MLP_SHM_FLOATS 41344
#define MLP_SHM_BYTES  (MLP_SHM_FLOATS * 4)
#define NGROUPS (NN / 8)          // 6250

__global__ __launch_bounds__(512) void mlp_kernel(
    const float* __restrict__ hin,
    const float* __restrict__ W1, const float* __restrict__ b1,
    const float* __restrict__ g1, const float* __restrict__ bt1,
    const float* __restrict__ m1, const float* __restrict__ v1,
    const float* __restrict__ W2, const float* __restrict__ b2,
    const float* __restrict__ gc, const float* __restrict__ bc,
    const float* __restrict__ mc, const float* __restrict__ vc,
    float* __restrict__ xout)
{
    extern __shared__ float sm[];
    float* W1s = sm;             // [64][128]   8192
    float* W2s = W1s + 8192;     // [128][64]   8192
    float* a1  = W2s + 8192;     // [128]
    float* c1  = a1 + 128;       // [128]
    float* a2  = c1 + 128;       // [64]
    float* c2  = a2 + 64;        // [64]
    float* xs  = c2 + 64;        // [16 warps][8][64]    8192
    float* hs  = xs + 8192;      // [16 warps][8][128]  16384

    const int tid  = threadIdx.x;
    const int warp = tid >> 5;
    const int lane = tid & 31;

    float* xs_w = xs + warp * 512;    // 8 x 64
    float* hs_w = hs + warp * 1024;   // 8 x 128

    for (int i = tid; i < 8192; i += 512) W1s[i] = W1[i];
    for (int i = tid; i < 8192; i += 512) W2s[i] = W2[i];
    if (tid < 128) {
        float a = g1[tid] * rsqrtf(v1[tid] + BN_EPS);
        a1[tid] = a;
        c1[tid] = (b1[tid] - m1[tid]) * a + bt1[tid];
    } else if (tid < 192) {
        int j = tid - 128;
        float a = gc[j] * rsqrtf(vc[j] + BN_EPS);
        a2[j] = a;
        c2[j] = (b2[j] - mc[j]) * a + bc[j];
    }
    __syncthreads();   // weights + consts staged (only block barrier)

    const int gwarp  = blockIdx.x * 16 + warp;
    const int nwarps = gridDim.x * 16;

    for (int grp = gwarp; grp < NGROUPS; grp += nwarps) {
        const int base = grp * 8;     // always + 8 <= NN

        // ---- load 8 node rows into private xs (coalesced LDG.128) ----
        #pragma unroll
        for (int j = 0; j < 4; j++) {
            const int idx = j * 32 + lane;        // float4 slot 0..127
            const int row = idx >> 4;
            const int c4  = idx & 15;
            const float4 v = *(const float4*)(hin + (size_t)(base + row) * 64 + c4 * 4);
            *(float4*)(xs_w + row * 64 + c4 * 4) = v;
        }
        __syncwarp();

        // ---- GEMM1: 8 nodes x (64 -> 128), bn+relu -> hs_w (FFMA2) ----
        {
            const int j0 = lane * 4;
            unsigned long long acc01[8], acc23[8];
            #pragma unroll
            for (int n = 0; n < 8; n++) { acc01[n] = 0ULL; acc23[n] = 0ULL; }

            for (int k4 = 0; k4 < 16; k4++) {
                ulonglong2 wk0 = *(const ulonglong2*)(W1s + (k4 * 4 + 0) * 128 + j0);
                ulonglong2 wk1 = *(const ulonglong2*)(W1s + (k4 * 4 + 1) * 128 + j0);
                ulonglong2 wk2 = *(const ulonglong2*)(W1s + (k4 * 4 + 2) * 128 + j0);
                ulonglong2 wk3 = *(const ulonglong2*)(W1s + (k4 * 4 + 3) * 128 + j0);
                #pragma unroll
                for (int n = 0; n < 8; n++) {
                    const float4 xv = *(const float4*)(xs_w + n * 64 + k4 * 4);
                    unsigned long long xp;
                    xp = pack2(xv.x);
                    acc01[n] = ffma2(xp, wk0.x, acc01[n]);
                    acc23[n] = ffma2(xp, wk0.y, acc23[n]);
                    xp = pack2(xv.y);
                    acc01[n] = ffma2(xp, wk1.x, acc01[n]);
                    acc23[n] = ffma2(xp, wk1.y, acc23[n]);
                    xp = pack2(xv.z);
                    acc01[n] = ffma2(xp, wk2.x, acc01[n]);
                    acc23[n] = ffma2(xp, wk2.y, acc23[n]);
                    xp = pack2(xv.w);
                    acc01[n] = ffma2(xp, wk3.x, acc01[n]);
                    acc23[n] = ffma2(xp, wk3.y, acc23[n]);
                }
            }
            const float4 A = *(const float4*)(a1 + j0);
            const float4 C = *(const float4*)(c1 + j0);
            #pragma unroll
            for (int n = 0; n < 8; n++) {
                float f0, f1, f2, f3;
                unpack2(acc01[n], f0, f1);
                unpack2(acc23[n], f2, f3);
                float4 h;
                h.x = fmaxf(fmaf(f0, A.x, C.x), 0.f);
                h.y = fmaxf(fmaf(f1, A.y, C.y), 0.f);
                h.z = fmaxf(fmaf(f2, A.z, C.z), 0.f);
                h.w = fmaxf(fmaf(f3, A.w, C.w), 0.f);
                *(float4*)(hs_w + n * 128 + j0) = h;
            }
        }
        __syncwarp();

        // ---- GEMM2: 8 nodes x (128 -> 64), bn+relu -> xout (FFMA2) ----
        // lane: j2=(lane&15)*4; half-warp picks 4 of the 8 nodes.
        {
            const int j2 = (lane & 15) * 4;
            const int nb = (lane >> 4) * 4;
            unsigned long long acc01[4], acc23[4];
            #pragma unroll
            for (int n = 0; n < 4; n++) { acc01[n] = 0ULL; acc23[n] = 0ULL; }

            for (int k4 = 0; k4 < 32; k4++) {
                ulonglong2 wk0 = *(const ulonglong2*)(W2s + (k4 * 4 + 0) * 64 + j2);
                ulonglong2 wk1 = *(const ulonglong2*)(W2s + (k4 * 4 + 1) * 64 + j2);
                ulonglong2 wk2 = *(const ulonglong2*)(W2s + (k4 * 4 + 2) * 64 + j2);
                ulonglong2 wk3 = *(const ulonglong2*)(W2s + (k4 * 4 + 3) * 64 + j2);
                #pragma unroll
                for (int n = 0; n < 4; n++) {
                    const float4 hv = *(const float4*)(hs_w + (nb + n) * 128 + k4 * 4);
                    unsigned long long xp;
                    xp = pack2(hv.x);
                    acc01[n] = ffma2(xp, wk0.x, acc01[n]);
                    acc23[n] = ffma2(xp, wk0.y, acc23[n]);
                    xp = pack2(hv.y);
                    acc01[n] = ffma2(xp, wk1.x, acc01[n]);
                    acc23[n] = ffma2(xp, wk1.y, acc23[n]);
                    xp = pack2(hv.z);
                    acc01[n] = ffma2(xp, wk2.x, acc01[n]);
                    acc23[n] = ffma2(xp, wk2.y, acc23[n]);
                    xp = pack2(hv.w);
                    acc01[n] = ffma2(xp, wk3.x, acc01[n]);
                    acc23[n] = ffma2(xp, wk3.y, acc23[n]);
                }
            }
            const float4 A = *(const float4*)(a2 + j2);
            const float4 C = *(const float4*)(c2 + j2);
            #pragma unroll
            for (int n = 0; n < 4; n++) {
                const int node = base + nb + n;
                float f0, f1, f2, f3;
                unpack2(acc01[n], f0, f1);
                unpack2(acc23[n], f2, f3);
                float4 o;
                o.x = fmaxf(fmaf(f0, A.x, C.x), 0.f);
                o.y = fmaxf(fmaf(f1, A.y, C.y), 0.f);
                o.z = fmaxf(fmaf(f2, A.z, C.z), 0.f);
                o.w = fmaxf(fmaf(f3, A.w, C.w), 0.f);
                *(float4*)(xout + (size_t)node * 64 + j2) = o;
            }
        }
        // next iteration's xs store is ordered by the next __syncwarp();
        // hs WAR is safe: every lane passes the post-xs syncwarp only after
        // finishing its own GEMM2 reads.
    }
}

// ---------------------------------------------------------------------------
// Register-tiled head (unchanged).
// ---------------------------------------------------------------------------
#define HEAD_SHM_FLOATS 32960
#define HEAD_SHM_BYTES  (HEAD_SHM_FLOATS * 4)

__global__ __launch_bounds__(512) void head_kernel(
    const float* __restrict__ x,
    const float* __restrict__ lin1_W, const float* __restrict__ lin1_b,
    const float* __restrict__ g,  const float* __restrict__ b,
    const float* __restrict__ m,  const float* __restrict__ v,
    const float* __restrict__ lin2_W, const float* __restrict__ lin2_b,
    float* __restrict__ out)
{
    extern __shared__ float sm[];
    float* W1s = sm;             // [64][64]
    float* W2s = W1s + 4096;     // [64][64] (cols 40..63 zero)
    float* a1  = W2s + 4096;     // [64]
    float* c1  = a1 + 64;        // [64]
    float* c2  = c1 + 64;        // [64]
    float* xs  = c2 + 64;        // [128][64]
    float* ts  = xs + 8192;      // [128][64]
    float* ls  = ts + 8192;      // [128][64]

    const int tid  = threadIdx.x;
    const int warp = tid >> 5;
    const int lane = tid & 31;

    for (int i = tid; i < 4096; i += 512) W1s[i] = lin1_W[i];
    for (int i = tid; i < 4096; i += 512) {
        int col = i & 63;
        W2s[i] = (col < CC) ? lin2_W[(i >> 6) * CC + col] : 0.0f;
    }
    if (tid < 64) {
        float a = g[tid] * rsqrtf(v[tid] + BN_EPS);
        a1[tid] = a;
        c1[tid] = (lin1_b[tid] - m[tid]) * a + b[tid];
    } else if (tid < 128) {
        int j = tid - 64;
        c2[j] = (j < CC) ? lin2_b[j] : 0.0f;
    }
    __syncthreads();

    const int ntiles = (NN + 127) >> 7;
    for (int tile = blockIdx.x; tile < ntiles; tile += gridDim.x) {
        const int base = tile << 7;

        for (int i = tid; i < 2048; i += 512) {
            int node = i >> 4;
            float4 vv;
            if (base + node < NN)
                vv = *(const float4*)(x + (size_t)(base + node) * 64 + (i & 15) * 4);
            else
                vv = make_float4(0.f, 0.f, 0.f, 0.f);
            *(float4*)(xs + i * 4) = vv;
        }
        __syncthreads();

        {
            const int j0 = lane * 2;
            float2 acc[8];
            #pragma unroll
            for (int n = 0; n < 8; n++) acc[n] = make_float2(0.f, 0.f);
            const float* xrow = xs + (warp * 8) * 64;

            for (int k4 = 0; k4 < 16; k4++) {
                const float2 w0 = *(const float2*)(W1s + (k4 * 4 + 0) * 64 + j0);
                const float2 w1 = *(const float2*)(W1s + (k4 * 4 + 1) * 64 + j0);
                const float2 w2 = *(const float2*)(W1s + (k4 * 4 + 2) * 64 + j0);
                const float2 w3 = *(const float2*)(W1s + (k4 * 4 + 3) * 64 + j0);
                #pragma unroll
                for (int n = 0; n < 8; n++) {
                    const float4 xv = *(const float4*)(xrow + n * 64 + k4 * 4);
                    acc[n].x = fmaf(xv.x, w0.x, acc[n].x);
                    acc[n].y = fmaf(xv.x, w0.y, acc[n].y);
                    acc[n].x = fmaf(xv.y, w1.x, acc[n].x);
                    acc[n].y = fmaf(xv.y, w1.y, acc[n].y);
                    acc[n].x = fmaf(xv.z, w2.x, acc[n].x);
                    acc[n].y = fmaf(xv.z, w2.y, acc[n].y);
                    acc[n].x = fmaf(xv.w, w3.x, acc[n].x);
                    acc[n].y = fmaf(xv.w, w3.y, acc[n].y);
                }
            }
            const float A0 = a1[j0], A1 = a1[j0 + 1];
            const float C0 = c1[j0], C1 = c1[j0 + 1];
            #pragma unroll
            for (int n = 0; n < 8; n++) {
                float2 t;
                t.x = fmaxf(fmaf(acc[n].x, A0, C0), 0.f);
                t.y = fmaxf(fmaf(acc[n].y, A1, C1), 0.f);
                *(float2*)(ts + (warp * 8 + n) * 64 + j0) = t;
            }
        }
        __syncthreads();

        {
            const int j0 = lane * 2;
            float2 acc[8];
            #pragma unroll
            for (int n = 0; n < 8; n++) acc[n] = make_float2(0.f, 0.f);
            const float* trow = ts + (warp * 8) * 64;

            for (int k4 = 0; k4 < 16; k4++) {
                const float2 w0 = *(const float2*)(W2s + (k4 * 4 + 0) * 64 + j0);
                const float2 w1 = *(const float2*)(W2s + (k4 * 4 + 1) * 64 + j0);
                const float2 w2 = *(const float2*)(W2s + (k4 * 4 + 2) * 64 + j0);
                const float2 w3 = *(const float2*)(W2s + (k4 * 4 + 3) * 64 + j0);
                #pragma unroll
                for (int n = 0; n < 8; n++) {
                    const float4 tv = *(const float4*)(trow + n * 64 + k4 * 4);
                    acc[n].x = fmaf(tv.x, w0.x, acc[n].x);
                    acc[n].y = fmaf(tv.x, w0.y, acc[n].y);
                    acc[n].x = fmaf(tv.y, w1.x, acc[n].x);
                    acc[n].y = fmaf(tv.y, w1.y, acc[n].y);
                    acc[n].x = fmaf(tv.z, w2.x, acc[n].x);
                    acc[n].y = fmaf(tv.z, w2.y, acc[n].y);
                    acc[n].x = fmaf(tv.w, w3.x, acc[n].x);
                    acc[n].y = fmaf(tv.w, w3.y, acc[n].y);
                }
            }
            const float C0 = c2[j0], C1 = c2[j0 + 1];
            #pragma unroll
            for (int n = 0; n < 8; n++) {
                float2 o;
                o.x = acc[n].x + C0;
                o.y = acc[n].y + C1;
                *(float2*)(ls + (warp * 8 + n) * 64 + j0) = o;
            }
        }
        __syncthreads();

        for (int n = 0; n < 8; n++) {
            const int node = base + warp * 8 + n;
            if (node >= NN) break;
            const float* lr = ls + (warp * 8 + n) * 64;
            float v0 = lr[lane];
            float v1 = (lane < CC - 32) ? lr[32 + lane] : -3.0e38f;
            float mx = fmaxf(v0, v1);
            #pragma unroll
            for (int o = 16; o > 0; o >>= 1)
                mx = fmaxf(mx, __shfl_xor_sync(0xffffffffu, mx, o));
            float s = expf(v0 - mx) + ((lane < CC - 32) ? expf(v1 - mx) : 0.f);
            #pragma unroll
            for (int o = 16; o > 0; o >>= 1)
                s += __shfl_xor_sync(0xffffffffu, s, o);
            const float lse = mx + logf(s);
            float* orow = out + (size_t)node * CC;
            orow[lane] = v0 - lse;
            if (lane < CC - 32) orow[32 + lane] = v1 - lse;
        }
        __syncthreads();
    }
}

// ---------------------------------------------------------------------------
extern "C" void kernel_launch(void* const* d_in, const int* in_sizes, int n_in,
                              void* d_out, int out_size) {
    const float* x = nullptr;
    const void*  ei = nullptr;
    const float* w24[2] = {nullptr, nullptr}; int n24 = 0;
    const float* p384[5] = {0};               int n384 = 0;
    const float* p192[5] = {0};               int n192 = 0;
    const float* p64[5]  = {0};               int n64 = 0;
    const float* lin1_W = nullptr;
    const float* lin2_W = nullptr;
    const float* lin2_b = nullptr;

    for (int i = 0; i < n_in; i++) {
        int s = in_sizes[i];
        const float* p = (const float*)d_in[i];
        if      (s == NN * FF)     x = p;
        else if (s == 2 * EE)      ei = d_in[i];
        else if (s == LL * FF * H2) { if (n24 < 2) w24[n24++] = p; }
        else if (s == LL * H2)     { if (n384 < 5) p384[n384++] = p; }
        else if (s == LL * HH)     { if (n192 < 5) p192[n192++] = p; }
        else if (s == HH * HH)     lin1_W = p;
        else if (s == HH)          { if (n64 < 5) p64[n64++] = p; }
        else if (s == HH * CC)     lin2_W = p;
        else if (s == CC)          lin2_b = p;
    }

    const float* W1s  = w24[0];
    const float* W2s  = w24[1];
    const float* b1s  = p384[0], *g1s = p384[1], *bt1s = p384[2],
               * m1s  = p384[3], *v1s = p384[4];
    const float* b2s  = p192[0], *gcs = p192[1], *bcs = p192[2],
               * mcs  = p192[3], *vcs = p192[4];
    const float* lin1_b = p64[0], *g_bn1 = p64[1], *b_bn1 = p64[2],
               * m_bn1  = p64[3], *v_bn1 = p64[4];

    if (!x || !ei || !W1s || !W2s || !lin1_W || !lin2_W || !lin2_b) return;

    float* gx;   cudaGetSymbolAddress((void**)&gx,   g_x);
    float* gagg; cudaGetSymbolAddress((void**)&gagg, g_agg);
    int*   gdeg; cudaGetSymbolAddress((void**)&gdeg, g_deg);

    cudaFuncSetAttribute(mlp_kernel,  cudaFuncAttributeMaxDynamicSharedMemorySize, MLP_SHM_BYTES);
    cudaFuncSetAttribute(head_kernel, cudaFuncAttributeMaxDynamicSharedMemorySize, HEAD_SHM_BYTES);

    detect_kernel<<<1, 256>>>((const long long*)ei);
    cudaMemsetAsync(gdeg, 0, NN * sizeof(int));
    fill_kernel<<<(EE + 255) / 256, 256>>>(ei);

    const int gather_blocks = (NN * 32 + 255) / 256;

    const float* cur = x;
    for (int l = 0; l < LL; l++) {
        gather_kernel<<<gather_blocks, 256>>>(cur, gagg);
        mlp_kernel<<<148, 512, MLP_SHM_BYTES>>>(
            gagg,
            W1s + (size_t)l * FF * H2,  b1s + (size_t)l * H2,
            g1s + (size_t)l * H2,       bt1s + (size_t)l * H2,
            m1s + (size_t)l * H2,       v1s + (size_t)l * H2,
            W2s + (size_t)l * H2 * HH,  b2s + (size_t)l * HH,
            gcs + (size_t)l * HH,       bcs + (size_t)l * HH,
            mcs + (size_t)l * HH,       vcs + (size_t)l * HH,
            gx);
        cur = gx;
    }

    head_kernel<<<148, 512, HEAD_SHM_BYTES>>>(
        gx, lin1_W, lin1_b, g_bn1, b_bn1, m_bn1, v_bn1, lin2_W, lin2_b,
        (float*)d_out);
}